// round 13
// baseline (speedup 1.0000x reference)
#include <cuda_runtime.h>
#include <cuda_fp16.h>

#define D 64
#define MAXN 50000
#define MAXE 800000
#define SCAN_B 1024
#define NB_MAX ((MAXN + SCAN_B - 1) / SCAN_B)
#define DBINS 256

// ---------------- device scratch (no allocation allowed) ----------------
__device__ __align__(16) __half g_h[MAXN * D];   // fp16 feature payload
__device__ float g_a[MAXN * D];
__device__ float g_as[MAXN];
__device__ float g_ad[MAXN];
__device__ int   g_deg[MAXN];
__device__ int   g_cur[MAXN];
__device__ int   g_offs[MAXN + 1];
__device__ int   g_bsums[NB_MAX];
__device__ int   g_csr[MAXE];
__device__ int   g_order[MAXN];       // nodes sorted by degree
__device__ int   g_dh[DBINS];         // degree histogram -> offsets
__device__ int   g_dcur[DBINS];
__device__ int   g_is64;

__device__ __forceinline__ float lrelu(float x, float s) { return x > 0.f ? x : s * x; }

__device__ __forceinline__ int edge_val(const void* eidx, int idx, int is64) {
    return is64 ? (int)((const long long*)eidx)[idx] : ((const int*)eidx)[idx];
}

__device__ __forceinline__ unsigned f2tf32(float f) {
    unsigned u;
    asm("cvt.rna.tf32.f32 %0, %1;" : "=r"(u) : "f"(f));
    return u;
}

// ---------------- init / CSR build ----------------
__global__ void init_kernel(const void* eidx, int n) {
    int i = blockIdx.x * blockDim.x + threadIdx.x;
    if (i < n) { g_deg[i] = 0; g_cur[i] = 0; }
    if (i < DBINS) { g_dh[i] = 0; g_dcur[i] = 0; }
    if (i == 0) {
        const long long* p = (const long long*)eidx;
        int ok = 1;
        #pragma unroll
        for (int k = 0; k < 32; k++) {
            long long v = p[k];
            if (v < 0 || v >= (long long)n) { ok = 0; break; }
        }
        g_is64 = ok;
    }
}

__global__ void hist_kernel(const void* eidx, int e) {
    int i = blockIdx.x * blockDim.x + threadIdx.x;
    if (i < e) {
        int d = edge_val(eidx, e + i, g_is64);
        atomicAdd(&g_deg[d], 1);
    }
}

__global__ void scan_block_kernel(int n) {
    __shared__ int wsum[32];
    int t = threadIdx.x, lane = t & 31, wid = t >> 5;
    int gid = blockIdx.x * SCAN_B + t;
    int v = (gid < n) ? g_deg[gid] : 0;
    int x = v;
    #pragma unroll
    for (int o = 1; o < 32; o <<= 1) {
        int y = __shfl_up_sync(0xffffffffu, x, o);
        if (lane >= o) x += y;
    }
    if (lane == 31) wsum[wid] = x;
    __syncthreads();
    if (wid == 0) {
        int s = wsum[lane];
        #pragma unroll
        for (int o = 1; o < 32; o <<= 1) {
            int y = __shfl_up_sync(0xffffffffu, s, o);
            if (lane >= o) s += y;
        }
        wsum[lane] = s;
    }
    __syncthreads();
    int incl = x + (wid > 0 ? wsum[wid - 1] : 0);
    if (gid < n) g_offs[gid] = incl - v;
    if (t == SCAN_B - 1) g_bsums[blockIdx.x] = incl;
}

__global__ void scan_fixup_kernel(int n, int e, int nb) {
    __shared__ int s_pre;
    int t = threadIdx.x, b = blockIdx.x;
    if (t < 32) {
        int p = 0;
        for (int i = t; i < b; i += 32) p += g_bsums[i];
        #pragma unroll
        for (int o = 16; o >= 1; o >>= 1)
            p += __shfl_xor_sync(0xffffffffu, p, o);
        if (t == 0) s_pre = p;
    }
    __syncthreads();
    int pre = s_pre;
    int gid = b * SCAN_B + t;
    if (gid < n) g_offs[gid] += pre;
    if (gid == 0) g_offs[n] = e;
}

__global__ void scatter_kernel(const void* eidx, int e) {
    int i = blockIdx.x * blockDim.x + threadIdx.x;
    if (i < e) {
        int is64 = g_is64;
        int d = edge_val(eidx, e + i, is64);
        int s = edge_val(eidx, i, is64);
        int pos = g_offs[d] + atomicAdd(&g_cur[d], 1);
        g_csr[pos] = s;
    }
}

// ---------------- degree-sort (counting sort, 256 bins) ----------------
__global__ void dhist_kernel(int n) {
    int i = blockIdx.x * blockDim.x + threadIdx.x;
    if (i < n) {
        int d = min(g_deg[i], DBINS - 1);
        atomicAdd(&g_dh[d], 1);
    }
}

// single block, 256 threads: exclusive scan of g_dh in place
__global__ void dscan_kernel() {
    __shared__ int wsum[8];
    int t = threadIdx.x, lane = t & 31, wid = t >> 5;
    int v = g_dh[t];
    int x = v;
    #pragma unroll
    for (int o = 1; o < 32; o <<= 1) {
        int y = __shfl_up_sync(0xffffffffu, x, o);
        if (lane >= o) x += y;
    }
    if (lane == 31) wsum[wid] = x;
    __syncthreads();
    if (wid == 0 && lane < 8) {
        int s = wsum[lane];
        #pragma unroll
        for (int o = 1; o < 8; o <<= 1) {
            int y = __shfl_up_sync(0xffu, s, o);
            if (lane >= o) s += y;
        }
        wsum[lane] = s;
    }
    __syncthreads();
    int incl = x + (wid > 0 ? wsum[wid - 1] : 0);
    g_dh[t] = incl - v;          // exclusive
}

__global__ void dscatter_kernel(int n) {
    int i = blockIdx.x * blockDim.x + threadIdx.x;
    if (i < n) {
        int d = min(g_deg[i], DBINS - 1);
        int pos = g_dh[d] + atomicAdd(&g_dcur[d], 1);
        g_order[pos] = i;
    }
}

// ---------------- GEMM: H = X @ W^T via tf32 mma.sync ----------------
#define XP 68
#define SX_F (128 * XP)
#define SW_F (D * XP)
#define GEMM_SMEM ((SX_F + SW_F) * 4)

__global__ void __launch_bounds__(256) gemm_kernel(
        const float* __restrict__ X, const float* __restrict__ W,
        const float* __restrict__ a_src, const float* __restrict__ a_dst, int n) {
    extern __shared__ __align__(16) unsigned smu[];
    unsigned* sX = smu;            // [r][k] tf32 bits, pitch XP
    unsigned* sW = smu + SX_F;     // [c][k] tf32 bits, pitch XP

    int t = threadIdx.x;
    int base = blockIdx.x * 128;

    {
        const float4* Xv = (const float4*)X;
        #pragma unroll
        for (int idx = t; idx < 128 * 16; idx += 256) {
            int r = idx >> 4, q = idx & 15;
            int gr = base + r;
            float4 v = make_float4(0.f, 0.f, 0.f, 0.f);
            if (gr < n) v = Xv[gr * 16 + q];
            uint4 u;
            u.x = f2tf32(v.x); u.y = f2tf32(v.y);
            u.z = f2tf32(v.z); u.w = f2tf32(v.w);
            *reinterpret_cast<uint4*>(&sX[r * XP + q * 4]) = u;
        }
    }
    {
        const float4* Wv = (const float4*)W;
        #pragma unroll
        for (int idx = t; idx < 64 * 16; idx += 256) {
            int c = idx >> 4, q = idx & 15;
            float4 v = Wv[idx];
            uint4 u;
            u.x = f2tf32(v.x); u.y = f2tf32(v.y);
            u.z = f2tf32(v.z); u.w = f2tf32(v.w);
            *reinterpret_cast<uint4*>(&sW[c * XP + q * 4]) = u;
        }
    }
    __syncthreads();

    int lane = t & 31;
    int wr   = (t >> 5) << 4;
    int gid  = lane >> 2;
    int tig  = lane & 3;

    float c[8][4];
    #pragma unroll
    for (int nt = 0; nt < 8; nt++)
        #pragma unroll
        for (int j = 0; j < 4; j++) c[nt][j] = 0.f;

    const unsigned* arow0 = &sX[(wr + gid) * XP + tig];
    const unsigned* arow1 = arow0 + 8 * XP;
    const unsigned* brow  = &sW[gid * XP + tig];

    #pragma unroll
    for (int ks = 0; ks < 8; ks++) {
        int k0 = ks * 8;
        unsigned a0 = arow0[k0];
        unsigned a1 = arow1[k0];
        unsigned a2 = arow0[k0 + 4];
        unsigned a3 = arow1[k0 + 4];
        #pragma unroll
        for (int nt = 0; nt < 8; nt++) {
            unsigned b0 = brow[nt * 8 * XP + k0];
            unsigned b1 = brow[nt * 8 * XP + k0 + 4];
            asm volatile(
                "mma.sync.aligned.m16n8k8.row.col.f32.tf32.tf32.f32 "
                "{%0,%1,%2,%3}, {%4,%5,%6,%7}, {%8,%9}, {%0,%1,%2,%3};"
                : "+f"(c[nt][0]), "+f"(c[nt][1]), "+f"(c[nt][2]), "+f"(c[nt][3])
                : "r"(a0), "r"(a1), "r"(a2), "r"(a3), "r"(b0), "r"(b1));
        }
    }

    int gr0 = base + wr + gid;
    int gr1 = gr0 + 8;
    float asp0 = 0.f, adp0 = 0.f, asp1 = 0.f, adp1 = 0.f;
    #pragma unroll
    for (int nt = 0; nt < 8; nt++) {
        int col = nt * 8 + tig * 2;
        float sa0 = a_src[col], sa1 = a_src[col + 1];
        float da0 = a_dst[col], da1 = a_dst[col + 1];
        asp0 += c[nt][0] * sa0 + c[nt][1] * sa1;
        adp0 += c[nt][0] * da0 + c[nt][1] * da1;
        asp1 += c[nt][2] * sa0 + c[nt][3] * sa1;
        adp1 += c[nt][2] * da0 + c[nt][3] * da1;

        __half2 h01 = __floats2half2_rn(c[nt][0], c[nt][1]);
        __half2 h23 = __floats2half2_rn(c[nt][2], c[nt][3]);
        if (gr0 < n) *reinterpret_cast<__half2*>(&g_h[gr0 * D + col]) = h01;
        if (gr1 < n) *reinterpret_cast<__half2*>(&g_h[gr1 * D + col]) = h23;
    }
    #pragma unroll
    for (int o = 1; o <= 2; o <<= 1) {
        asp0 += __shfl_xor_sync(0xffffffffu, asp0, o);
        adp0 += __shfl_xor_sync(0xffffffffu, adp0, o);
        asp1 += __shfl_xor_sync(0xffffffffu, asp1, o);
        adp1 += __shfl_xor_sync(0xffffffffu, adp1, o);
    }
    if (tig == 0) {
        if (gr0 < n) { g_as[gr0] = asp0; g_ad[gr0] = adp0; }
        if (gr1 < n) { g_as[gr1] = asp1; g_ad[gr1] = adp1; }
    }
}

// ---------------- aggregation: 4 degree-sorted nodes/warp, 8 lanes/node ---
__global__ void agg_kernel(const float* __restrict__ b, int n, int last,
                           const float* __restrict__ Wout,
                           const float* __restrict__ bout,
                           float* __restrict__ out) {
    int wid_g = (blockIdx.x * blockDim.x + threadIdx.x) >> 5;
    int lane = threadIdx.x & 31;
    if (wid_g * 4 >= n) return;
    int sub = lane >> 3, sl = lane & 7;
    int idx = wid_g * 4 + sub;
    bool valid = idx < n;
    int vc = g_order[valid ? idx : (n - 1)];   // degree-sorted node id

    int beg = g_offs[vc];
    int deg = valid ? (g_offs[vc + 1] - beg) : 0;
    float adv = g_ad[vc];
    int c0 = sl * 8;

    float acc[8];
    float denom;
    {
        float w0 = valid ? __expf(lrelu(g_as[vc] + adv, 0.2f)) : 0.f;
        denom = w0;
        uint4 pk = *reinterpret_cast<const uint4*>(&g_h[vc * D + c0]);
        const __half2* hp = reinterpret_cast<const __half2*>(&pk);
        #pragma unroll
        for (int q = 0; q < 4; q++) {
            float2 f = __half22float2(hp[q]);
            acc[q * 2]     = w0 * f.x;
            acc[q * 2 + 1] = w0 * f.y;
        }
    }

    int mx = deg;
    #pragma unroll
    for (int o = 16; o >= 1; o >>= 1)
        mx = max(mx, __shfl_xor_sync(0xffffffffu, mx, o));

    int i = 0;
    for (; i + 4 <= mx; i += 4) {
        bool b0 = i < deg, b1 = i + 1 < deg, b2 = i + 2 < deg, b3 = i + 3 < deg;
        int p = beg + i;
        int s0 = b0 ? g_csr[p]     : vc;
        int s1 = b1 ? g_csr[p + 1] : vc;
        int s2 = b2 ? g_csr[p + 2] : vc;
        int s3 = b3 ? g_csr[p + 3] : vc;
        float as0 = g_as[s0], as1 = g_as[s1], as2 = g_as[s2], as3 = g_as[s3];
        uint4 p0 = *reinterpret_cast<const uint4*>(&g_h[s0 * D + c0]);
        uint4 p1 = *reinterpret_cast<const uint4*>(&g_h[s1 * D + c0]);
        uint4 p2 = *reinterpret_cast<const uint4*>(&g_h[s2 * D + c0]);
        uint4 p3 = *reinterpret_cast<const uint4*>(&g_h[s3 * D + c0]);
        float e0 = b0 ? __expf(lrelu(as0 + adv, 0.2f)) : 0.f;
        float e1 = b1 ? __expf(lrelu(as1 + adv, 0.2f)) : 0.f;
        float e2 = b2 ? __expf(lrelu(as2 + adv, 0.2f)) : 0.f;
        float e3 = b3 ? __expf(lrelu(as3 + adv, 0.2f)) : 0.f;
        const __half2* h0 = reinterpret_cast<const __half2*>(&p0);
        const __half2* h1 = reinterpret_cast<const __half2*>(&p1);
        const __half2* h2 = reinterpret_cast<const __half2*>(&p2);
        const __half2* h3 = reinterpret_cast<const __half2*>(&p3);
        denom += (e0 + e1) + (e2 + e3);
        #pragma unroll
        for (int q = 0; q < 4; q++) {
            float2 f0 = __half22float2(h0[q]);
            float2 f1 = __half22float2(h1[q]);
            float2 f2 = __half22float2(h2[q]);
            float2 f3 = __half22float2(h3[q]);
            acc[q * 2]     += (e0 * f0.x + e1 * f1.x) + (e2 * f2.x + e3 * f3.x);
            acc[q * 2 + 1] += (e0 * f0.y + e1 * f1.y) + (e2 * f2.y + e3 * f3.y);
        }
    }
    for (; i < mx; i++) {
        bool bv = i < deg;
        int p = beg + i;
        int s0 = bv ? g_csr[p] : vc;
        float e0 = bv ? __expf(lrelu(g_as[s0] + adv, 0.2f)) : 0.f;
        uint4 pk = *reinterpret_cast<const uint4*>(&g_h[s0 * D + c0]);
        const __half2* hp = reinterpret_cast<const __half2*>(&pk);
        denom += e0;
        #pragma unroll
        for (int q = 0; q < 4; q++) {
            float2 f = __half22float2(hp[q]);
            acc[q * 2]     += e0 * f.x;
            acc[q * 2 + 1] += e0 * f.y;
        }
    }

    float inv = valid ? (1.0f / denom) : 0.f;
    float o8[8];
    #pragma unroll
    for (int q = 0; q < 8; q++)
        o8[q] = lrelu(acc[q] * inv + b[c0 + q], 0.01f);

    if (!last) {
        if (valid) {
            float4 va; va.x = o8[0]; va.y = o8[1]; va.z = o8[2]; va.w = o8[3];
            float4 vb; vb.x = o8[4]; vb.y = o8[5]; vb.z = o8[6]; vb.w = o8[7];
            *reinterpret_cast<float4*>(&g_a[vc * D + c0])     = va;
            *reinterpret_cast<float4*>(&g_a[vc * D + c0 + 4]) = vb;
        }
    } else {
        float s = 0.f;
        #pragma unroll
        for (int q = 0; q < 8; q++) s += o8[q] * Wout[c0 + q];
        #pragma unroll
        for (int o = 4; o >= 1; o >>= 1)
            s += __shfl_xor_sync(0xffffffffu, s, o);
        if (sl == 0 && valid) out[vc] = s + bout[0];
    }
}

// ---------------- launch ----------------
extern "C" void kernel_launch(void* const* d_in, const int* in_sizes, int n_in,
                              void* d_out, int out_size) {
    const float* x = (const float*)d_in[0];
    const float* W[3]    = {(const float*)d_in[1], (const float*)d_in[5], (const float*)d_in[9]};
    const float* asrc[3] = {(const float*)d_in[2], (const float*)d_in[6], (const float*)d_in[10]};
    const float* adst[3] = {(const float*)d_in[3], (const float*)d_in[7], (const float*)d_in[11]};
    const float* bias[3] = {(const float*)d_in[4], (const float*)d_in[8], (const float*)d_in[12]};
    const float* Wout = (const float*)d_in[13];
    const float* bout = (const float*)d_in[14];
    const void*  eidx = d_in[15];

    int n = in_sizes[0] / D;
    int e = in_sizes[15] / 2;

    void* a_ptr = nullptr;
    cudaGetSymbolAddress(&a_ptr, g_a);
    const float* abuf = (const float*)a_ptr;

    cudaFuncSetAttribute(gemm_kernel,
                         cudaFuncAttributeMaxDynamicSharedMemorySize, GEMM_SMEM);

    int nb = (n + SCAN_B - 1) / SCAN_B;
    int eb = (e + 255) / 256;
    int zb = (n + 255) / 256;
    int gemm_b = (n + 127) / 128;
    int agg_b  = ((n + 3) / 4 * 32 + 255) / 256;

    init_kernel<<<zb, 256>>>(eidx, n);
    hist_kernel<<<eb, 256>>>(eidx, e);
    scan_block_kernel<<<nb, SCAN_B>>>(n);
    gemm_kernel<<<gemm_b, 256, GEMM_SMEM>>>(x, W[0], asrc[0], adst[0], n);  // profiled
    dhist_kernel<<<zb, 256>>>(n);
    dscan_kernel<<<1, DBINS>>>();
    scan_fixup_kernel<<<nb, SCAN_B>>>(n, e, nb);
    dscatter_kernel<<<zb, 256>>>(n);
    scatter_kernel<<<eb, 256>>>(eidx, e);
    agg_kernel<<<agg_b, 256>>>(bias[0], n, 0, Wout, bout, (float*)d_out);

    for (int l = 1; l < 3; l++) {
        gemm_kernel<<<gemm_b, 256, GEMM_SMEM>>>(abuf, W[l], asrc[l], adst[l], n);
        agg_kernel<<<agg_b, 256>>>(bias[l], n, (l == 2) ? 1 : 0,
                                   Wout, bout, (float*)d_out);
    }
}

// round 14
// speedup vs baseline: 1.1368x; 1.1368x over previous
#include <cuda_runtime.h>
#include <cuda_fp16.h>

#define D 64
#define MAXN 50000
#define MAXE 800000
#define SCAN_B 1024
#define NB_MAX ((MAXN + SCAN_B - 1) / SCAN_B)

// ---------------- device scratch (no allocation allowed) ----------------
__device__ __align__(16) __half g_h[MAXN * D];   // fp16 feature payload
__device__ float g_a[MAXN * D];
__device__ float g_as[MAXN];
__device__ float g_ad[MAXN];
__device__ int   g_deg[MAXN];
__device__ int   g_cur[MAXN];
__device__ int   g_offs[MAXN + 1];
__device__ int   g_bsums[NB_MAX];
__device__ int   g_csr[MAXE];
__device__ int   g_is64;

__device__ __forceinline__ float lrelu(float x, float s) { return x > 0.f ? x : s * x; }

__device__ __forceinline__ int edge_val(const void* eidx, int idx, int is64) {
    return is64 ? (int)((const long long*)eidx)[idx] : ((const int*)eidx)[idx];
}

__device__ __forceinline__ unsigned f2tf32(float f) {
    unsigned u;
    asm("cvt.rna.tf32.f32 %0, %1;" : "=r"(u) : "f"(f));
    return u;
}

// ---------------- init / CSR build ----------------
__global__ void init_kernel(const void* eidx, int n) {
    int i = blockIdx.x * blockDim.x + threadIdx.x;
    if (i < n) { g_deg[i] = 0; g_cur[i] = 0; }
    if (i == 0) {
        const long long* p = (const long long*)eidx;
        int ok = 1;
        #pragma unroll
        for (int k = 0; k < 32; k++) {
            long long v = p[k];
            if (v < 0 || v >= (long long)n) { ok = 0; break; }
        }
        g_is64 = ok;
    }
}

__global__ void hist_kernel(const void* eidx, int e) {
    int i = blockIdx.x * blockDim.x + threadIdx.x;
    if (i < e) {
        int d = edge_val(eidx, e + i, g_is64);
        atomicAdd(&g_deg[d], 1);
    }
}

__global__ void scan_block_kernel(int n) {
    __shared__ int wsum[32];
    int t = threadIdx.x, lane = t & 31, wid = t >> 5;
    int gid = blockIdx.x * SCAN_B + t;
    int v = (gid < n) ? g_deg[gid] : 0;
    int x = v;
    #pragma unroll
    for (int o = 1; o < 32; o <<= 1) {
        int y = __shfl_up_sync(0xffffffffu, x, o);
        if (lane >= o) x += y;
    }
    if (lane == 31) wsum[wid] = x;
    __syncthreads();
    if (wid == 0) {
        int s = wsum[lane];
        #pragma unroll
        for (int o = 1; o < 32; o <<= 1) {
            int y = __shfl_up_sync(0xffffffffu, s, o);
            if (lane >= o) s += y;
        }
        wsum[lane] = s;
    }
    __syncthreads();
    int incl = x + (wid > 0 ? wsum[wid - 1] : 0);
    if (gid < n) g_offs[gid] = incl - v;
    if (t == SCAN_B - 1) g_bsums[blockIdx.x] = incl;
}

__global__ void scan_fixup_kernel(int n, int e, int nb) {
    __shared__ int s_pre;
    int t = threadIdx.x, b = blockIdx.x;
    if (t < 32) {
        int p = 0;
        for (int i = t; i < b; i += 32) p += g_bsums[i];
        #pragma unroll
        for (int o = 16; o >= 1; o >>= 1)
            p += __shfl_xor_sync(0xffffffffu, p, o);
        if (t == 0) s_pre = p;
    }
    __syncthreads();
    int pre = s_pre;
    int gid = b * SCAN_B + t;
    if (gid < n) g_offs[gid] += pre;
    if (gid == 0) g_offs[n] = e;
}

__global__ void scatter_kernel(const void* eidx, int e) {
    int i = blockIdx.x * blockDim.x + threadIdx.x;
    if (i < e) {
        int is64 = g_is64;
        int d = edge_val(eidx, e + i, is64);
        int s = edge_val(eidx, i, is64);
        int pos = g_offs[d] + atomicAdd(&g_cur[d], 1);
        g_csr[pos] = s;
    }
}

// ---------------- GEMM: H = X @ W^T via tf32 mma.sync ----------------
// 512 threads = 16 warps, 128 rows/block. Warp = 16 rows x 32 cols
// (4 n-tiles m16n8k8, 8 k-steps); warp pairs split the 64 cols.
// Operands pre-converted to tf32 at staging. Logits combined via smem.
#define XP 68
#define SX_F (128 * XP)
#define SW_F (D * XP)
#define GEMM_SMEM ((SX_F + SW_F) * 4)

__global__ void __launch_bounds__(512) gemm_kernel(
        const float* __restrict__ X, const float* __restrict__ W,
        const float* __restrict__ a_src, const float* __restrict__ a_dst, int n) {
    extern __shared__ __align__(16) unsigned smu[];
    unsigned* sX = smu;            // [r][k] tf32 bits, pitch XP
    unsigned* sW = smu + SX_F;     // [c][k] tf32 bits, pitch XP
    __shared__ float s_as[2][128], s_ad[2][128];

    int t = threadIdx.x;
    int base = blockIdx.x * 128;

    // stage X as tf32 bits
    {
        const float4* Xv = (const float4*)X;
        #pragma unroll
        for (int idx = t; idx < 128 * 16; idx += 512) {
            int r = idx >> 4, q = idx & 15;
            int gr = base + r;
            float4 v = make_float4(0.f, 0.f, 0.f, 0.f);
            if (gr < n) v = Xv[gr * 16 + q];
            uint4 u;
            u.x = f2tf32(v.x); u.y = f2tf32(v.y);
            u.z = f2tf32(v.z); u.w = f2tf32(v.w);
            *reinterpret_cast<uint4*>(&sX[r * XP + q * 4]) = u;
        }
    }
    // stage W as tf32 bits
    {
        const float4* Wv = (const float4*)W;
        #pragma unroll
        for (int idx = t; idx < 64 * 16; idx += 512) {
            int c = idx >> 4, q = idx & 15;
            float4 v = Wv[idx];
            uint4 u;
            u.x = f2tf32(v.x); u.y = f2tf32(v.y);
            u.z = f2tf32(v.z); u.w = f2tf32(v.w);
            *reinterpret_cast<uint4*>(&sW[c * XP + q * 4]) = u;
        }
    }
    __syncthreads();

    int lane = t & 31;
    int w    = t >> 5;              // 0..15
    int wr   = (w >> 1) << 4;       // row base: 0..112
    int ch   = (w & 1) << 5;        // col half: 0 or 32
    int gid  = lane >> 2;           // 0..7
    int tig  = lane & 3;            // 0..3

    float c[4][4];
    #pragma unroll
    for (int nt = 0; nt < 4; nt++)
        #pragma unroll
        for (int j = 0; j < 4; j++) c[nt][j] = 0.f;

    const unsigned* arow0 = &sX[(wr + gid) * XP + tig];
    const unsigned* arow1 = arow0 + 8 * XP;
    const unsigned* brow  = &sW[(ch + gid) * XP + tig];

    #pragma unroll
    for (int ks = 0; ks < 8; ks++) {
        int k0 = ks * 8;
        unsigned a0 = arow0[k0];
        unsigned a1 = arow1[k0];
        unsigned a2 = arow0[k0 + 4];
        unsigned a3 = arow1[k0 + 4];
        #pragma unroll
        for (int nt = 0; nt < 4; nt++) {
            unsigned b0 = brow[nt * 8 * XP + k0];
            unsigned b1 = brow[nt * 8 * XP + k0 + 4];
            asm volatile(
                "mma.sync.aligned.m16n8k8.row.col.f32.tf32.tf32.f32 "
                "{%0,%1,%2,%3}, {%4,%5,%6,%7}, {%8,%9}, {%0,%1,%2,%3};"
                : "+f"(c[nt][0]), "+f"(c[nt][1]), "+f"(c[nt][2]), "+f"(c[nt][3])
                : "r"(a0), "r"(a1), "r"(a2), "r"(a3), "r"(b0), "r"(b1));
        }
    }

    // epilogue: partial logits over this warp's 32 cols + fp16 payload store
    int gr0 = base + wr + gid;
    int gr1 = gr0 + 8;
    float asp0 = 0.f, adp0 = 0.f, asp1 = 0.f, adp1 = 0.f;
    #pragma unroll
    for (int nt = 0; nt < 4; nt++) {
        int col = ch + nt * 8 + tig * 2;
        float sa0 = a_src[col], sa1 = a_src[col + 1];
        float da0 = a_dst[col], da1 = a_dst[col + 1];
        asp0 += c[nt][0] * sa0 + c[nt][1] * sa1;
        adp0 += c[nt][0] * da0 + c[nt][1] * da1;
        asp1 += c[nt][2] * sa0 + c[nt][3] * sa1;
        adp1 += c[nt][2] * da0 + c[nt][3] * da1;

        __half2 h01 = __floats2half2_rn(c[nt][0], c[nt][1]);
        __half2 h23 = __floats2half2_rn(c[nt][2], c[nt][3]);
        if (gr0 < n) *reinterpret_cast<__half2*>(&g_h[gr0 * D + col]) = h01;
        if (gr1 < n) *reinterpret_cast<__half2*>(&g_h[gr1 * D + col]) = h23;
    }
    #pragma unroll
    for (int o = 1; o <= 2; o <<= 1) {
        asp0 += __shfl_xor_sync(0xffffffffu, asp0, o);
        adp0 += __shfl_xor_sync(0xffffffffu, adp0, o);
        asp1 += __shfl_xor_sync(0xffffffffu, asp1, o);
        adp1 += __shfl_xor_sync(0xffffffffu, adp1, o);
    }
    if (tig == 0) {
        s_as[w & 1][wr + gid]     = asp0;
        s_as[w & 1][wr + gid + 8] = asp1;
        s_ad[w & 1][wr + gid]     = adp0;
        s_ad[w & 1][wr + gid + 8] = adp1;
    }
    __syncthreads();
    if (t < 128) {
        int gr = base + t;
        if (gr < n) {
            g_as[gr] = s_as[0][t] + s_as[1][t];
            g_ad[gr] = s_ad[0][t] + s_ad[1][t];
        }
    }
}

// ---------------- aggregation: 4 nodes/warp, 8 lanes/node, x4 batched -----
__global__ void agg_kernel(const float* __restrict__ b, int n, int last,
                           const float* __restrict__ Wout,
                           const float* __restrict__ bout,
                           float* __restrict__ out) {
    int wid_g = (blockIdx.x * blockDim.x + threadIdx.x) >> 5;
    int lane = threadIdx.x & 31;
    if (wid_g * 4 >= n) return;
    int sub = lane >> 3, sl = lane & 7;
    int v = wid_g * 4 + sub;
    bool valid = v < n;
    int vc = valid ? v : (n - 1);

    int beg = g_offs[vc];
    int deg = valid ? (g_offs[vc + 1] - beg) : 0;
    float adv = g_ad[vc];
    int c0 = sl * 8;

    float acc[8];
    float denom;
    {
        float w0 = valid ? __expf(lrelu(g_as[vc] + adv, 0.2f)) : 0.f;
        denom = w0;
        uint4 pk = *reinterpret_cast<const uint4*>(&g_h[vc * D + c0]);
        const __half2* hp = reinterpret_cast<const __half2*>(&pk);
        #pragma unroll
        for (int q = 0; q < 4; q++) {
            float2 f = __half22float2(hp[q]);
            acc[q * 2]     = w0 * f.x;
            acc[q * 2 + 1] = w0 * f.y;
        }
    }

    int mx = deg;
    #pragma unroll
    for (int o = 16; o >= 1; o >>= 1)
        mx = max(mx, __shfl_xor_sync(0xffffffffu, mx, o));

    int i = 0;
    for (; i + 4 <= mx; i += 4) {
        bool b0 = i < deg, b1 = i + 1 < deg, b2 = i + 2 < deg, b3 = i + 3 < deg;
        int p = beg + i;
        int s0 = b0 ? g_csr[p]     : vc;
        int s1 = b1 ? g_csr[p + 1] : vc;
        int s2 = b2 ? g_csr[p + 2] : vc;
        int s3 = b3 ? g_csr[p + 3] : vc;
        float as0 = g_as[s0], as1 = g_as[s1], as2 = g_as[s2], as3 = g_as[s3];
        uint4 p0 = *reinterpret_cast<const uint4*>(&g_h[s0 * D + c0]);
        uint4 p1 = *reinterpret_cast<const uint4*>(&g_h[s1 * D + c0]);
        uint4 p2 = *reinterpret_cast<const uint4*>(&g_h[s2 * D + c0]);
        uint4 p3 = *reinterpret_cast<const uint4*>(&g_h[s3 * D + c0]);
        float e0 = b0 ? __expf(lrelu(as0 + adv, 0.2f)) : 0.f;
        float e1 = b1 ? __expf(lrelu(as1 + adv, 0.2f)) : 0.f;
        float e2 = b2 ? __expf(lrelu(as2 + adv, 0.2f)) : 0.f;
        float e3 = b3 ? __expf(lrelu(as3 + adv, 0.2f)) : 0.f;
        const __half2* h0 = reinterpret_cast<const __half2*>(&p0);
        const __half2* h1 = reinterpret_cast<const __half2*>(&p1);
        const __half2* h2 = reinterpret_cast<const __half2*>(&p2);
        const __half2* h3 = reinterpret_cast<const __half2*>(&p3);
        denom += (e0 + e1) + (e2 + e3);
        #pragma unroll
        for (int q = 0; q < 4; q++) {
            float2 f0 = __half22float2(h0[q]);
            float2 f1 = __half22float2(h1[q]);
            float2 f2 = __half22float2(h2[q]);
            float2 f3 = __half22float2(h3[q]);
            acc[q * 2]     += (e0 * f0.x + e1 * f1.x) + (e2 * f2.x + e3 * f3.x);
            acc[q * 2 + 1] += (e0 * f0.y + e1 * f1.y) + (e2 * f2.y + e3 * f3.y);
        }
    }
    for (; i < mx; i++) {
        bool bv = i < deg;
        int p = beg + i;
        int s0 = bv ? g_csr[p] : vc;
        float e0 = bv ? __expf(lrelu(g_as[s0] + adv, 0.2f)) : 0.f;
        uint4 pk = *reinterpret_cast<const uint4*>(&g_h[s0 * D + c0]);
        const __half2* hp = reinterpret_cast<const __half2*>(&pk);
        denom += e0;
        #pragma unroll
        for (int q = 0; q < 4; q++) {
            float2 f = __half22float2(hp[q]);
            acc[q * 2]     += e0 * f.x;
            acc[q * 2 + 1] += e0 * f.y;
        }
    }

    float inv = valid ? (1.0f / denom) : 0.f;
    float o8[8];
    #pragma unroll
    for (int q = 0; q < 8; q++)
        o8[q] = lrelu(acc[q] * inv + b[c0 + q], 0.01f);

    if (!last) {
        if (valid) {
            float4 va; va.x = o8[0]; va.y = o8[1]; va.z = o8[2]; va.w = o8[3];
            float4 vb; vb.x = o8[4]; vb.y = o8[5]; vb.z = o8[6]; vb.w = o8[7];
            *reinterpret_cast<float4*>(&g_a[v * D + c0])     = va;
            *reinterpret_cast<float4*>(&g_a[v * D + c0 + 4]) = vb;
        }
    } else {
        float s = 0.f;
        #pragma unroll
        for (int q = 0; q < 8; q++) s += o8[q] * Wout[c0 + q];
        #pragma unroll
        for (int o = 4; o >= 1; o >>= 1)
            s += __shfl_xor_sync(0xffffffffu, s, o);
        if (sl == 0 && valid) out[v] = s + bout[0];
    }
}

// ---------------- launch ----------------
extern "C" void kernel_launch(void* const* d_in, const int* in_sizes, int n_in,
                              void* d_out, int out_size) {
    const float* x = (const float*)d_in[0];
    const float* W[3]    = {(const float*)d_in[1], (const float*)d_in[5], (const float*)d_in[9]};
    const float* asrc[3] = {(const float*)d_in[2], (const float*)d_in[6], (const float*)d_in[10]};
    const float* adst[3] = {(const float*)d_in[3], (const float*)d_in[7], (const float*)d_in[11]};
    const float* bias[3] = {(const float*)d_in[4], (const float*)d_in[8], (const float*)d_in[12]};
    const float* Wout = (const float*)d_in[13];
    const float* bout = (const float*)d_in[14];
    const void*  eidx = d_in[15];

    int n = in_sizes[0] / D;
    int e = in_sizes[15] / 2;

    void* a_ptr = nullptr;
    cudaGetSymbolAddress(&a_ptr, g_a);
    const float* abuf = (const float*)a_ptr;

    cudaFuncSetAttribute(gemm_kernel,
                         cudaFuncAttributeMaxDynamicSharedMemorySize, GEMM_SMEM);

    int nb = (n + SCAN_B - 1) / SCAN_B;
    int eb = (e + 255) / 256;
    int zb = (n + 255) / 256;
    int gemm_b = (n + 127) / 128;
    int agg_b  = ((n + 3) / 4 * 32 + 255) / 256;

    init_kernel<<<zb, 256>>>(eidx, n);
    hist_kernel<<<eb, 256>>>(eidx, e);
    scan_block_kernel<<<nb, SCAN_B>>>(n);
    gemm_kernel<<<gemm_b, 512, GEMM_SMEM>>>(x, W[0], asrc[0], adst[0], n);  // profiled
    scan_fixup_kernel<<<nb, SCAN_B>>>(n, e, nb);
    scatter_kernel<<<eb, 256>>>(eidx, e);
    agg_kernel<<<agg_b, 256>>>(bias[0], n, 0, Wout, bout, (float*)d_out);

    for (int l = 1; l < 3; l++) {
        gemm_kernel<<<gemm_b, 512, GEMM_SMEM>>>(abuf, W[l], asrc[l], adst[l], n);
        agg_kernel<<<agg_b, 256>>>(bias[l], n, (l == 2) ? 1 : 0,
                                   Wout, bout, (float*)d_out);
    }
}

// round 15
// speedup vs baseline: 1.2055x; 1.0604x over previous
#include <cuda_runtime.h>
#include <cuda_fp16.h>

#define D 64
#define MAXN 50000
#define MAXE 800000
#define SCAN_B 1024
#define NB_MAX ((MAXN + SCAN_B - 1) / SCAN_B)

// ---------------- device scratch (no allocation allowed) ----------------
__device__ __align__(16) __half g_h[MAXN * D];   // fp16 feature payload
__device__ float g_a[MAXN * D];
__device__ float g_as[MAXN];
__device__ float g_ad[MAXN];
__device__ int   g_deg[MAXN];
__device__ int   g_offs[MAXN + 1];    // after scatter: g_offs[v] = segment END
__device__ int   g_bsums[NB_MAX];
__device__ int   g_csr[MAXE];
__device__ int   g_is64;

__device__ __forceinline__ float lrelu(float x, float s) { return x > 0.f ? x : s * x; }

__device__ __forceinline__ int edge_val(const void* eidx, int idx, int is64) {
    return is64 ? (int)((const long long*)eidx)[idx] : ((const int*)eidx)[idx];
}

__device__ __forceinline__ unsigned f2tf32(float f) {
    unsigned u;
    asm("cvt.rna.tf32.f32 %0, %1;" : "=r"(u) : "f"(f));
    return u;
}

// ---------------- init / CSR build ----------------
__global__ void init_kernel(const void* eidx, int n) {
    int i = blockIdx.x * blockDim.x + threadIdx.x;
    if (i < n) g_deg[i] = 0;
    if (i == 0) {
        const long long* p = (const long long*)eidx;
        int ok = 1;
        #pragma unroll
        for (int k = 0; k < 32; k++) {
            long long v = p[k];
            if (v < 0 || v >= (long long)n) { ok = 0; break; }
        }
        g_is64 = ok;
    }
}

__global__ void hist_kernel(const void* eidx, int e) {
    int i = blockIdx.x * blockDim.x + threadIdx.x;
    if (i < e) {
        int d = edge_val(eidx, e + i, g_is64);
        atomicAdd(&g_deg[d], 1);
    }
}

__global__ void scan_block_kernel(int n) {
    __shared__ int wsum[32];
    int t = threadIdx.x, lane = t & 31, wid = t >> 5;
    int gid = blockIdx.x * SCAN_B + t;
    int v = (gid < n) ? g_deg[gid] : 0;
    int x = v;
    #pragma unroll
    for (int o = 1; o < 32; o <<= 1) {
        int y = __shfl_up_sync(0xffffffffu, x, o);
        if (lane >= o) x += y;
    }
    if (lane == 31) wsum[wid] = x;
    __syncthreads();
    if (wid == 0) {
        int s = wsum[lane];
        #pragma unroll
        for (int o = 1; o < 32; o <<= 1) {
            int y = __shfl_up_sync(0xffffffffu, s, o);
            if (lane >= o) s += y;
        }
        wsum[lane] = s;
    }
    __syncthreads();
    int incl = x + (wid > 0 ? wsum[wid - 1] : 0);
    if (gid < n) g_offs[gid] = incl - v;
    if (t == SCAN_B - 1) g_bsums[blockIdx.x] = incl;
}

__global__ void scan_fixup_kernel(int n, int e, int nb) {
    __shared__ int s_pre;
    int t = threadIdx.x, b = blockIdx.x;
    if (t < 32) {
        int p = 0;
        for (int i = t; i < b; i += 32) p += g_bsums[i];
        #pragma unroll
        for (int o = 16; o >= 1; o >>= 1)
            p += __shfl_xor_sync(0xffffffffu, p, o);
        if (t == 0) s_pre = p;
    }
    __syncthreads();
    int pre = s_pre;
    int gid = b * SCAN_B + t;
    if (gid < n) g_offs[gid] += pre;
    if (gid == 0) g_offs[n] = e;
}

// scatter bumps g_offs[d] directly: afterwards g_offs[v] = segment end.
__global__ void scatter_kernel(const void* eidx, int e) {
    int i = blockIdx.x * blockDim.x + threadIdx.x;
    if (i < e) {
        int is64 = g_is64;
        int d = edge_val(eidx, e + i, is64);
        int s = edge_val(eidx, i, is64);
        int pos = atomicAdd(&g_offs[d], 1);
        g_csr[pos] = s;
    }
}

// ---------------- GEMM: H = X @ W^T via tf32 mma.sync (R12 config) -------
#define XP 68
#define SX_F (128 * XP)
#define SW_F (D * XP)
#define GEMM_SMEM ((SX_F + SW_F) * 4)

__global__ void __launch_bounds__(256) gemm_kernel(
        const float* __restrict__ X, const float* __restrict__ W,
        const float* __restrict__ a_src, const float* __restrict__ a_dst, int n) {
    extern __shared__ __align__(16) unsigned smu[];
    unsigned* sX = smu;            // [r][k] tf32 bits, pitch XP
    unsigned* sW = smu + SX_F;     // [c][k] tf32 bits, pitch XP

    int t = threadIdx.x;
    int base = blockIdx.x * 128;

    {
        const float4* Xv = (const float4*)X;
        #pragma unroll
        for (int idx = t; idx < 128 * 16; idx += 256) {
            int r = idx >> 4, q = idx & 15;
            int gr = base + r;
            float4 v = make_float4(0.f, 0.f, 0.f, 0.f);
            if (gr < n) v = Xv[gr * 16 + q];
            uint4 u;
            u.x = f2tf32(v.x); u.y = f2tf32(v.y);
            u.z = f2tf32(v.z); u.w = f2tf32(v.w);
            *reinterpret_cast<uint4*>(&sX[r * XP + q * 4]) = u;
        }
    }
    {
        const float4* Wv = (const float4*)W;
        #pragma unroll
        for (int idx = t; idx < 64 * 16; idx += 256) {
            int c = idx >> 4, q = idx & 15;
            float4 v = Wv[idx];
            uint4 u;
            u.x = f2tf32(v.x); u.y = f2tf32(v.y);
            u.z = f2tf32(v.z); u.w = f2tf32(v.w);
            *reinterpret_cast<uint4*>(&sW[c * XP + q * 4]) = u;
        }
    }
    __syncthreads();

    int lane = t & 31;
    int wr   = (t >> 5) << 4;
    int gid  = lane >> 2;
    int tig  = lane & 3;

    float c[8][4];
    #pragma unroll
    for (int nt = 0; nt < 8; nt++)
        #pragma unroll
        for (int j = 0; j < 4; j++) c[nt][j] = 0.f;

    const unsigned* arow0 = &sX[(wr + gid) * XP + tig];
    const unsigned* arow1 = arow0 + 8 * XP;
    const unsigned* brow  = &sW[gid * XP + tig];

    #pragma unroll
    for (int ks = 0; ks < 8; ks++) {
        int k0 = ks * 8;
        unsigned a0 = arow0[k0];
        unsigned a1 = arow1[k0];
        unsigned a2 = arow0[k0 + 4];
        unsigned a3 = arow1[k0 + 4];
        #pragma unroll
        for (int nt = 0; nt < 8; nt++) {
            unsigned b0 = brow[nt * 8 * XP + k0];
            unsigned b1 = brow[nt * 8 * XP + k0 + 4];
            asm volatile(
                "mma.sync.aligned.m16n8k8.row.col.f32.tf32.tf32.f32 "
                "{%0,%1,%2,%3}, {%4,%5,%6,%7}, {%8,%9}, {%0,%1,%2,%3};"
                : "+f"(c[nt][0]), "+f"(c[nt][1]), "+f"(c[nt][2]), "+f"(c[nt][3])
                : "r"(a0), "r"(a1), "r"(a2), "r"(a3), "r"(b0), "r"(b1));
        }
    }

    int gr0 = base + wr + gid;
    int gr1 = gr0 + 8;
    float asp0 = 0.f, adp0 = 0.f, asp1 = 0.f, adp1 = 0.f;
    #pragma unroll
    for (int nt = 0; nt < 8; nt++) {
        int col = nt * 8 + tig * 2;
        float sa0 = a_src[col], sa1 = a_src[col + 1];
        float da0 = a_dst[col], da1 = a_dst[col + 1];
        asp0 += c[nt][0] * sa0 + c[nt][1] * sa1;
        adp0 += c[nt][0] * da0 + c[nt][1] * da1;
        asp1 += c[nt][2] * sa0 + c[nt][3] * sa1;
        adp1 += c[nt][2] * da0 + c[nt][3] * da1;

        __half2 h01 = __floats2half2_rn(c[nt][0], c[nt][1]);
        __half2 h23 = __floats2half2_rn(c[nt][2], c[nt][3]);
        if (gr0 < n) *reinterpret_cast<__half2*>(&g_h[gr0 * D + col]) = h01;
        if (gr1 < n) *reinterpret_cast<__half2*>(&g_h[gr1 * D + col]) = h23;
    }
    #pragma unroll
    for (int o = 1; o <= 2; o <<= 1) {
        asp0 += __shfl_xor_sync(0xffffffffu, asp0, o);
        adp0 += __shfl_xor_sync(0xffffffffu, adp0, o);
        asp1 += __shfl_xor_sync(0xffffffffu, asp1, o);
        adp1 += __shfl_xor_sync(0xffffffffu, adp1, o);
    }
    if (tig == 0) {
        if (gr0 < n) { g_as[gr0] = asp0; g_ad[gr0] = adp0; }
        if (gr1 < n) { g_as[gr1] = asp1; g_ad[gr1] = adp1; }
    }
}

// ---------------- aggregation: 4 nodes/warp, 8 lanes/node, x4 batched -----
// g_offs[v] = segment end; beg = end - g_deg[v]. RO-cache gathers via __ldg.
__global__ void agg_kernel(const float* __restrict__ b, int n, int last,
                           const float* __restrict__ Wout,
                           const float* __restrict__ bout,
                           float* __restrict__ out) {
    int wid_g = (blockIdx.x * blockDim.x + threadIdx.x) >> 5;
    int lane = threadIdx.x & 31;
    if (wid_g * 4 >= n) return;
    int sub = lane >> 3, sl = lane & 7;
    int v = wid_g * 4 + sub;
    bool valid = v < n;
    int vc = valid ? v : (n - 1);

    int end = __ldg(&g_offs[vc]);
    int dg  = __ldg(&g_deg[vc]);
    int beg = end - dg;
    int deg = valid ? dg : 0;
    float adv = g_ad[vc];
    int c0 = sl * 8;

    float acc[8];
    float denom;
    {
        float w0 = valid ? __expf(lrelu(g_as[vc] + adv, 0.2f)) : 0.f;
        denom = w0;
        uint4 pk = __ldg(reinterpret_cast<const uint4*>(&g_h[vc * D + c0]));
        const __half2* hp = reinterpret_cast<const __half2*>(&pk);
        #pragma unroll
        for (int q = 0; q < 4; q++) {
            float2 f = __half22float2(hp[q]);
            acc[q * 2]     = w0 * f.x;
            acc[q * 2 + 1] = w0 * f.y;
        }
    }

    int mx = deg;
    #pragma unroll
    for (int o = 16; o >= 1; o >>= 1)
        mx = max(mx, __shfl_xor_sync(0xffffffffu, mx, o));

    int i = 0;
    for (; i + 4 <= mx; i += 4) {
        bool b0 = i < deg, b1 = i + 1 < deg, b2 = i + 2 < deg, b3 = i + 3 < deg;
        int p = beg + i;
        int s0 = b0 ? __ldg(&g_csr[p])     : vc;
        int s1 = b1 ? __ldg(&g_csr[p + 1]) : vc;
        int s2 = b2 ? __ldg(&g_csr[p + 2]) : vc;
        int s3 = b3 ? __ldg(&g_csr[p + 3]) : vc;
        float as0 = __ldg(&g_as[s0]), as1 = __ldg(&g_as[s1]);
        float as2 = __ldg(&g_as[s2]), as3 = __ldg(&g_as[s3]);
        uint4 p0 = __ldg(reinterpret_cast<const uint4*>(&g_h[s0 * D + c0]));
        uint4 p1 = __ldg(reinterpret_cast<const uint4*>(&g_h[s1 * D + c0]));
        uint4 p2 = __ldg(reinterpret_cast<const uint4*>(&g_h[s2 * D + c0]));
        uint4 p3 = __ldg(reinterpret_cast<const uint4*>(&g_h[s3 * D + c0]));
        float e0 = b0 ? __expf(lrelu(as0 + adv, 0.2f)) : 0.f;
        float e1 = b1 ? __expf(lrelu(as1 + adv, 0.2f)) : 0.f;
        float e2 = b2 ? __expf(lrelu(as2 + adv, 0.2f)) : 0.f;
        float e3 = b3 ? __expf(lrelu(as3 + adv, 0.2f)) : 0.f;
        const __half2* h0 = reinterpret_cast<const __half2*>(&p0);
        const __half2* h1 = reinterpret_cast<const __half2*>(&p1);
        const __half2* h2 = reinterpret_cast<const __half2*>(&p2);
        const __half2* h3 = reinterpret_cast<const __half2*>(&p3);
        denom += (e0 + e1) + (e2 + e3);
        #pragma unroll
        for (int q = 0; q < 4; q++) {
            float2 f0 = __half22float2(h0[q]);
            float2 f1 = __half22float2(h1[q]);
            float2 f2 = __half22float2(h2[q]);
            float2 f3 = __half22float2(h3[q]);
            acc[q * 2]     += (e0 * f0.x + e1 * f1.x) + (e2 * f2.x + e3 * f3.x);
            acc[q * 2 + 1] += (e0 * f0.y + e1 * f1.y) + (e2 * f2.y + e3 * f3.y);
        }
    }
    for (; i < mx; i++) {
        bool bv = i < deg;
        int p = beg + i;
        int s0 = bv ? __ldg(&g_csr[p]) : vc;
        float e0 = bv ? __expf(lrelu(__ldg(&g_as[s0]) + adv, 0.2f)) : 0.f;
        uint4 pk = __ldg(reinterpret_cast<const uint4*>(&g_h[s0 * D + c0]));
        const __half2* hp = reinterpret_cast<const __half2*>(&pk);
        denom += e0;
        #pragma unroll
        for (int q = 0; q < 4; q++) {
            float2 f = __half22float2(hp[q]);
            acc[q * 2]     += e0 * f.x;
            acc[q * 2 + 1] += e0 * f.y;
        }
    }

    float inv = valid ? (1.0f / denom) : 0.f;
    float o8[8];
    #pragma unroll
    for (int q = 0; q < 8; q++)
        o8[q] = lrelu(acc[q] * inv + b[c0 + q], 0.01f);

    if (!last) {
        if (valid) {
            float4 va; va.x = o8[0]; va.y = o8[1]; va.z = o8[2]; va.w = o8[3];
            float4 vb; vb.x = o8[4]; vb.y = o8[5]; vb.z = o8[6]; vb.w = o8[7];
            *reinterpret_cast<float4*>(&g_a[v * D + c0])     = va;
            *reinterpret_cast<float4*>(&g_a[v * D + c0 + 4]) = vb;
        }
    } else {
        float s = 0.f;
        #pragma unroll
        for (int q = 0; q < 8; q++) s += o8[q] * Wout[c0 + q];
        #pragma unroll
        for (int o = 4; o >= 1; o >>= 1)
            s += __shfl_xor_sync(0xffffffffu, s, o);
        if (sl == 0 && valid) out[v] = s + bout[0];
    }
}

// ---------------- launch ----------------
extern "C" void kernel_launch(void* const* d_in, const int* in_sizes, int n_in,
                              void* d_out, int out_size) {
    const float* x = (const float*)d_in[0];
    const float* W[3]    = {(const float*)d_in[1], (const float*)d_in[5], (const float*)d_in[9]};
    const float* asrc[3] = {(const float*)d_in[2], (const float*)d_in[6], (const float*)d_in[10]};
    const float* adst[3] = {(const float*)d_in[3], (const float*)d_in[7], (const float*)d_in[11]};
    const float* bias[3] = {(const float*)d_in[4], (const float*)d_in[8], (const float*)d_in[12]};
    const float* Wout = (const float*)d_in[13];
    const float* bout = (const float*)d_in[14];
    const void*  eidx = d_in[15];

    int n = in_sizes[0] / D;
    int e = in_sizes[15] / 2;

    void* a_ptr = nullptr;
    cudaGetSymbolAddress(&a_ptr, g_a);
    const float* abuf = (const float*)a_ptr;

    cudaFuncSetAttribute(gemm_kernel,
                         cudaFuncAttributeMaxDynamicSharedMemorySize, GEMM_SMEM);

    int nb = (n + SCAN_B - 1) / SCAN_B;
    int eb = (e + 255) / 256;
    int zb = (n + 255) / 256;
    int gemm_b = (n + 127) / 128;
    int agg_b  = ((n + 3) / 4 * 32 + 255) / 256;

    init_kernel<<<zb, 256>>>(eidx, n);
    hist_kernel<<<eb, 256>>>(eidx, e);
    scan_block_kernel<<<nb, SCAN_B>>>(n);
    gemm_kernel<<<gemm_b, 256, GEMM_SMEM>>>(x, W[0], asrc[0], adst[0], n);  // profiled
    scan_fixup_kernel<<<nb, SCAN_B>>>(n, e, nb);
    scatter_kernel<<<eb, 256>>>(eidx, e);
    agg_kernel<<<agg_b, 256>>>(bias[0], n, 0, Wout, bout, (float*)d_out);

    for (int l = 1; l < 3; l++) {
        gemm_kernel<<<gemm_b, 256, GEMM_SMEM>>>(abuf, W[l], asrc[l], adst[l], n);
        agg_kernel<<<agg_b, 256>>>(bias[l], n, (l == 2) ? 1 : 0,
                                   Wout, bout, (float*)d_out);
    }
}

// round 16
// speedup vs baseline: 1.2285x; 1.0191x over previous
#include <cuda_runtime.h>
#include <cuda_fp16.h>

#define D 64
#define MAXN 50000
#define MAXE 800000
#define SCAN_B 1024
#define NB_MAX ((MAXN + SCAN_B - 1) / SCAN_B)

// ---------------- device scratch (no allocation allowed) ----------------
__device__ __align__(16) __half g_h[MAXN * D];   // fp16 feature payload
__device__ float g_a[MAXN * D];
__device__ float g_as[MAXN];
__device__ float g_ad[MAXN];
__device__ int   g_deg[MAXN];
__device__ int   g_offs[MAXN + 1];    // after scatter: g_offs[v] = segment END
__device__ int   g_bsums[NB_MAX];
__device__ int   g_csr[MAXE];
__device__ int   g_is64;

__device__ __forceinline__ float lrelu(float x, float s) { return x > 0.f ? x : s * x; }

__device__ __forceinline__ int edge_val(const void* eidx, int idx, int is64) {
    return is64 ? (int)((const long long*)eidx)[idx] : ((const int*)eidx)[idx];
}

__device__ __forceinline__ unsigned f2tf32(float f) {
    unsigned u;
    asm("cvt.rna.tf32.f32 %0, %1;" : "=r"(u) : "f"(f));
    return u;
}

// ---------------- init / CSR build ----------------
__global__ void init_kernel(const void* eidx, int n) {
    int i = blockIdx.x * blockDim.x + threadIdx.x;
    if (i < n) g_deg[i] = 0;
    if (i == 0) {
        const long long* p = (const long long*)eidx;
        int ok = 1;
        #pragma unroll
        for (int k = 0; k < 32; k++) {
            long long v = p[k];
            if (v < 0 || v >= (long long)n) { ok = 0; break; }
        }
        g_is64 = ok;
    }
}

__global__ void hist_kernel(const void* eidx, int e) {
    int i = blockIdx.x * blockDim.x + threadIdx.x;
    if (i < e) {
        int d = edge_val(eidx, e + i, g_is64);
        atomicAdd(&g_deg[d], 1);
    }
}

__global__ void scan_block_kernel(int n) {
    __shared__ int wsum[32];
    int t = threadIdx.x, lane = t & 31, wid = t >> 5;
    int gid = blockIdx.x * SCAN_B + t;
    int v = (gid < n) ? g_deg[gid] : 0;
    int x = v;
    #pragma unroll
    for (int o = 1; o < 32; o <<= 1) {
        int y = __shfl_up_sync(0xffffffffu, x, o);
        if (lane >= o) x += y;
    }
    if (lane == 31) wsum[wid] = x;
    __syncthreads();
    if (wid == 0) {
        int s = wsum[lane];
        #pragma unroll
        for (int o = 1; o < 32; o <<= 1) {
            int y = __shfl_up_sync(0xffffffffu, s, o);
            if (lane >= o) s += y;
        }
        wsum[lane] = s;
    }
    __syncthreads();
    int incl = x + (wid > 0 ? wsum[wid - 1] : 0);
    if (gid < n) g_offs[gid] = incl - v;
    if (t == SCAN_B - 1) g_bsums[blockIdx.x] = incl;
}

__global__ void scan_fixup_kernel(int n, int e, int nb) {
    __shared__ int s_pre;
    int t = threadIdx.x, b = blockIdx.x;
    if (t < 32) {
        int p = 0;
        for (int i = t; i < b; i += 32) p += g_bsums[i];
        #pragma unroll
        for (int o = 16; o >= 1; o >>= 1)
            p += __shfl_xor_sync(0xffffffffu, p, o);
        if (t == 0) s_pre = p;
    }
    __syncthreads();
    int pre = s_pre;
    int gid = b * SCAN_B + t;
    if (gid < n) g_offs[gid] += pre;
    if (gid == 0) g_offs[n] = e;
}

// scatter bumps g_offs[d] directly: afterwards g_offs[v] = segment end.
__global__ void scatter_kernel(const void* eidx, int e) {
    int i = blockIdx.x * blockDim.x + threadIdx.x;
    if (i < e) {
        int is64 = g_is64;
        int d = edge_val(eidx, e + i, is64);
        int s = edge_val(eidx, i, is64);
        int pos = atomicAdd(&g_offs[d], 1);
        g_csr[pos] = s;
    }
}

// ---------------- GEMM: H = X @ W^T via tf32 mma.sync -------------------
#define XP 68
#define SX_F (128 * XP)
#define SW_F (D * XP)
#define GEMM_SMEM ((SX_F + SW_F) * 4)

__global__ void __launch_bounds__(256) gemm_kernel(
        const float* __restrict__ X, const float* __restrict__ W,
        const float* __restrict__ a_src, const float* __restrict__ a_dst, int n) {
    extern __shared__ __align__(16) unsigned smu[];
    unsigned* sX = smu;            // [r][k] tf32 bits, pitch XP
    unsigned* sW = smu + SX_F;     // [c][k] tf32 bits, pitch XP

    int t = threadIdx.x;
    int base = blockIdx.x * 128;

    {
        const float4* Xv = (const float4*)X;
        #pragma unroll
        for (int idx = t; idx < 128 * 16; idx += 256) {
            int r = idx >> 4, q = idx & 15;
            int gr = base + r;
            float4 v = make_float4(0.f, 0.f, 0.f, 0.f);
            if (gr < n) v = Xv[gr * 16 + q];
            uint4 u;
            u.x = f2tf32(v.x); u.y = f2tf32(v.y);
            u.z = f2tf32(v.z); u.w = f2tf32(v.w);
            *reinterpret_cast<uint4*>(&sX[r * XP + q * 4]) = u;
        }
    }
    {
        const float4* Wv = (const float4*)W;
        #pragma unroll
        for (int idx = t; idx < 64 * 16; idx += 256) {
            int c = idx >> 4, q = idx & 15;
            float4 v = Wv[idx];
            uint4 u;
            u.x = f2tf32(v.x); u.y = f2tf32(v.y);
            u.z = f2tf32(v.z); u.w = f2tf32(v.w);
            *reinterpret_cast<uint4*>(&sW[c * XP + q * 4]) = u;
        }
    }
    __syncthreads();

    int lane = t & 31;
    int wr   = (t >> 5) << 4;
    int gid  = lane >> 2;
    int tig  = lane & 3;

    float c[8][4];
    #pragma unroll
    for (int nt = 0; nt < 8; nt++)
        #pragma unroll
        for (int j = 0; j < 4; j++) c[nt][j] = 0.f;

    const unsigned* arow0 = &sX[(wr + gid) * XP + tig];
    const unsigned* arow1 = arow0 + 8 * XP;
    const unsigned* brow  = &sW[gid * XP + tig];

    #pragma unroll
    for (int ks = 0; ks < 8; ks++) {
        int k0 = ks * 8;
        unsigned a0 = arow0[k0];
        unsigned a1 = arow1[k0];
        unsigned a2 = arow0[k0 + 4];
        unsigned a3 = arow1[k0 + 4];
        #pragma unroll
        for (int nt = 0; nt < 8; nt++) {
            unsigned b0 = brow[nt * 8 * XP + k0];
            unsigned b1 = brow[nt * 8 * XP + k0 + 4];
            asm volatile(
                "mma.sync.aligned.m16n8k8.row.col.f32.tf32.tf32.f32 "
                "{%0,%1,%2,%3}, {%4,%5,%6,%7}, {%8,%9}, {%0,%1,%2,%3};"
                : "+f"(c[nt][0]), "+f"(c[nt][1]), "+f"(c[nt][2]), "+f"(c[nt][3])
                : "r"(a0), "r"(a1), "r"(a2), "r"(a3), "r"(b0), "r"(b1));
        }
    }

    int gr0 = base + wr + gid;
    int gr1 = gr0 + 8;
    float asp0 = 0.f, adp0 = 0.f, asp1 = 0.f, adp1 = 0.f;
    #pragma unroll
    for (int nt = 0; nt < 8; nt++) {
        int col = nt * 8 + tig * 2;
        float sa0 = a_src[col], sa1 = a_src[col + 1];
        float da0 = a_dst[col], da1 = a_dst[col + 1];
        asp0 += c[nt][0] * sa0 + c[nt][1] * sa1;
        adp0 += c[nt][0] * da0 + c[nt][1] * da1;
        asp1 += c[nt][2] * sa0 + c[nt][3] * sa1;
        adp1 += c[nt][2] * da0 + c[nt][3] * da1;

        __half2 h01 = __floats2half2_rn(c[nt][0], c[nt][1]);
        __half2 h23 = __floats2half2_rn(c[nt][2], c[nt][3]);
        if (gr0 < n) *reinterpret_cast<__half2*>(&g_h[gr0 * D + col]) = h01;
        if (gr1 < n) *reinterpret_cast<__half2*>(&g_h[gr1 * D + col]) = h23;
    }
    #pragma unroll
    for (int o = 1; o <= 2; o <<= 1) {
        asp0 += __shfl_xor_sync(0xffffffffu, asp0, o);
        adp0 += __shfl_xor_sync(0xffffffffu, adp0, o);
        asp1 += __shfl_xor_sync(0xffffffffu, asp1, o);
        adp1 += __shfl_xor_sync(0xffffffffu, adp1, o);
    }
    if (tig == 0) {
        if (gr0 < n) { g_as[gr0] = asp0; g_ad[gr0] = adp0; }
        if (gr1 < n) { g_as[gr1] = asp1; g_ad[gr1] = adp1; }
    }
}

// ---------------- aggregation: 4 nodes/warp, 8 lanes/node, x4 batched -----
__global__ void agg_kernel(const float* __restrict__ b, int n, int last,
                           const float* __restrict__ Wout,
                           const float* __restrict__ bout,
                           float* __restrict__ out) {
    int wid_g = (blockIdx.x * blockDim.x + threadIdx.x) >> 5;
    int lane = threadIdx.x & 31;
    if (wid_g * 4 >= n) return;
    int sub = lane >> 3, sl = lane & 7;
    int v = wid_g * 4 + sub;
    bool valid = v < n;
    int vc = valid ? v : (n - 1);

    int end = __ldg(&g_offs[vc]);
    int dg  = __ldg(&g_deg[vc]);
    int beg = end - dg;
    int deg = valid ? dg : 0;
    float adv = g_ad[vc];
    int c0 = sl * 8;

    float acc[8];
    float denom;
    {
        float w0 = valid ? __expf(lrelu(g_as[vc] + adv, 0.2f)) : 0.f;
        denom = w0;
        uint4 pk = __ldg(reinterpret_cast<const uint4*>(&g_h[vc * D + c0]));
        const __half2* hp = reinterpret_cast<const __half2*>(&pk);
        #pragma unroll
        for (int q = 0; q < 4; q++) {
            float2 f = __half22float2(hp[q]);
            acc[q * 2]     = w0 * f.x;
            acc[q * 2 + 1] = w0 * f.y;
        }
    }

    int mx = deg;
    #pragma unroll
    for (int o = 16; o >= 1; o >>= 1)
        mx = max(mx, __shfl_xor_sync(0xffffffffu, mx, o));

    int i = 0;
    for (; i + 4 <= mx; i += 4) {
        bool b0 = i < deg, b1 = i + 1 < deg, b2 = i + 2 < deg, b3 = i + 3 < deg;
        int p = beg + i;
        int s0 = b0 ? __ldg(&g_csr[p])     : vc;
        int s1 = b1 ? __ldg(&g_csr[p + 1]) : vc;
        int s2 = b2 ? __ldg(&g_csr[p + 2]) : vc;
        int s3 = b3 ? __ldg(&g_csr[p + 3]) : vc;
        float as0 = __ldg(&g_as[s0]), as1 = __ldg(&g_as[s1]);
        float as2 = __ldg(&g_as[s2]), as3 = __ldg(&g_as[s3]);
        uint4 p0 = __ldg(reinterpret_cast<const uint4*>(&g_h[s0 * D + c0]));
        uint4 p1 = __ldg(reinterpret_cast<const uint4*>(&g_h[s1 * D + c0]));
        uint4 p2 = __ldg(reinterpret_cast<const uint4*>(&g_h[s2 * D + c0]));
        uint4 p3 = __ldg(reinterpret_cast<const uint4*>(&g_h[s3 * D + c0]));
        float e0 = b0 ? __expf(lrelu(as0 + adv, 0.2f)) : 0.f;
        float e1 = b1 ? __expf(lrelu(as1 + adv, 0.2f)) : 0.f;
        float e2 = b2 ? __expf(lrelu(as2 + adv, 0.2f)) : 0.f;
        float e3 = b3 ? __expf(lrelu(as3 + adv, 0.2f)) : 0.f;
        const __half2* h0 = reinterpret_cast<const __half2*>(&p0);
        const __half2* h1 = reinterpret_cast<const __half2*>(&p1);
        const __half2* h2 = reinterpret_cast<const __half2*>(&p2);
        const __half2* h3 = reinterpret_cast<const __half2*>(&p3);
        denom += (e0 + e1) + (e2 + e3);
        #pragma unroll
        for (int q = 0; q < 4; q++) {
            float2 f0 = __half22float2(h0[q]);
            float2 f1 = __half22float2(h1[q]);
            float2 f2 = __half22float2(h2[q]);
            float2 f3 = __half22float2(h3[q]);
            acc[q * 2]     += (e0 * f0.x + e1 * f1.x) + (e2 * f2.x + e3 * f3.x);
            acc[q * 2 + 1] += (e0 * f0.y + e1 * f1.y) + (e2 * f2.y + e3 * f3.y);
        }
    }
    for (; i < mx; i++) {
        bool bv = i < deg;
        int p = beg + i;
        int s0 = bv ? __ldg(&g_csr[p]) : vc;
        float e0 = bv ? __expf(lrelu(__ldg(&g_as[s0]) + adv, 0.2f)) : 0.f;
        uint4 pk = __ldg(reinterpret_cast<const uint4*>(&g_h[s0 * D + c0]));
        const __half2* hp = reinterpret_cast<const __half2*>(&pk);
        denom += e0;
        #pragma unroll
        for (int q = 0; q < 4; q++) {
            float2 f = __half22float2(hp[q]);
            acc[q * 2]     += e0 * f.x;
            acc[q * 2 + 1] += e0 * f.y;
        }
    }

    float inv = valid ? (1.0f / denom) : 0.f;
    float o8[8];
    #pragma unroll
    for (int q = 0; q < 8; q++)
        o8[q] = lrelu(acc[q] * inv + b[c0 + q], 0.01f);

    if (!last) {
        if (valid) {
            float4 va; va.x = o8[0]; va.y = o8[1]; va.z = o8[2]; va.w = o8[3];
            float4 vb; vb.x = o8[4]; vb.y = o8[5]; vb.z = o8[6]; vb.w = o8[7];
            *reinterpret_cast<float4*>(&g_a[v * D + c0])     = va;
            *reinterpret_cast<float4*>(&g_a[v * D + c0 + 4]) = vb;
        }
    } else {
        float s = 0.f;
        #pragma unroll
        for (int q = 0; q < 8; q++) s += o8[q] * Wout[c0 + q];
        #pragma unroll
        for (int o = 4; o >= 1; o >>= 1)
            s += __shfl_xor_sync(0xffffffffu, s, o);
        if (sl == 0 && valid) out[v] = s + bout[0];
    }
}

// ---------------- launch: fork-join overlap of CSR chain with gemm0 -------
extern "C" void kernel_launch(void* const* d_in, const int* in_sizes, int n_in,
                              void* d_out, int out_size) {
    const float* x = (const float*)d_in[0];
    const float* W[3]    = {(const float*)d_in[1], (const float*)d_in[5], (const float*)d_in[9]};
    const float* asrc[3] = {(const float*)d_in[2], (const float*)d_in[6], (const float*)d_in[10]};
    const float* adst[3] = {(const float*)d_in[3], (const float*)d_in[7], (const float*)d_in[11]};
    const float* bias[3] = {(const float*)d_in[4], (const float*)d_in[8], (const float*)d_in[12]};
    const float* Wout = (const float*)d_in[13];
    const float* bout = (const float*)d_in[14];
    const void*  eidx = d_in[15];

    int n = in_sizes[0] / D;
    int e = in_sizes[15] / 2;

    void* a_ptr = nullptr;
    cudaGetSymbolAddress(&a_ptr, g_a);
    const float* abuf = (const float*)a_ptr;

    cudaFuncSetAttribute(gemm_kernel,
                         cudaFuncAttributeMaxDynamicSharedMemorySize, GEMM_SMEM);

    // Create side stream + events per call (host-side only; legal mid-capture
    // under relaxed exchange; kernel_launch is invoked only a handful of times).
    cudaStream_t s2 = nullptr;
    cudaEvent_t evFork = nullptr, evJoin = nullptr;
    {
        cudaStreamCaptureMode mode = cudaStreamCaptureModeRelaxed;
        cudaThreadExchangeStreamCaptureMode(&mode);
        cudaStreamCreateWithFlags(&s2, cudaStreamNonBlocking);
        cudaEventCreateWithFlags(&evFork, cudaEventDisableTiming);
        cudaEventCreateWithFlags(&evJoin, cudaEventDisableTiming);
        cudaThreadExchangeStreamCaptureMode(&mode);
    }

    int nb = (n + SCAN_B - 1) / SCAN_B;
    int eb = (e + 255) / 256;
    int zb = (n + 255) / 256;
    int gemm_b = (n + 127) / 128;
    int agg_b  = ((n + 3) / 4 * 32 + 255) / 256;

    // fork: CSR chain on s2, gemm0 on default stream
    cudaEventRecord(evFork, 0);
    cudaStreamWaitEvent(s2, evFork, 0);

    init_kernel<<<zb, 256, 0, s2>>>(eidx, n);
    hist_kernel<<<eb, 256, 0, s2>>>(eidx, e);
    scan_block_kernel<<<nb, SCAN_B, 0, s2>>>(n);
    scan_fixup_kernel<<<nb, SCAN_B, 0, s2>>>(n, e, nb);
    scatter_kernel<<<eb, 256, 0, s2>>>(eidx, e);
    cudaEventRecord(evJoin, s2);

    gemm_kernel<<<gemm_b, 256, GEMM_SMEM>>>(x, W[0], asrc[0], adst[0], n);

    // join before agg0 (needs CSR + gemm0)
    cudaStreamWaitEvent(0, evJoin, 0);
    agg_kernel<<<agg_b, 256>>>(bias[0], n, 0, Wout, bout, (float*)d_out);

    for (int l = 1; l < 3; l++) {
        gemm_kernel<<<gemm_b, 256, GEMM_SMEM>>>(abuf, W[l], asrc[l], adst[l], n);
        agg_kernel<<<agg_b, 256>>>(bias[l], n, (l == 2) ? 1 : 0,
                                   Wout, bout, (float*)d_out);
    }
}

// round 17
// speedup vs baseline: 1.2407x; 1.0100x over previous
#include <cuda_runtime.h>
#include <cuda_fp16.h>

#define D 64
#define MAXN 50000
#define MAXE 800000
#define SCAN_B 1024
#define NB_MAX ((MAXN + SCAN_B - 1) / SCAN_B)

// ---------------- device scratch (no allocation allowed) ----------------
__device__ __align__(16) __half g_h[MAXN * D];   // fp16 feature payload
__device__ float g_a[MAXN * D];
__device__ float g_as[MAXN];
__device__ float g_ad[MAXN];
__device__ int   g_deg[MAXN];
__device__ int   g_offs[MAXN + 1];    // after scatter: g_offs[v] = segment END
__device__ volatile int g_fsum[NB_MAX];  // published (block inclusive sum + 1)
__device__ int   g_csr[MAXE];
__device__ int   g_is64;

__device__ __forceinline__ float lrelu(float x, float s) { return x > 0.f ? x : s * x; }

__device__ __forceinline__ int edge_val(const void* eidx, int idx, int is64) {
    return is64 ? (int)((const long long*)eidx)[idx] : ((const int*)eidx)[idx];
}

__device__ __forceinline__ unsigned f2tf32(float f) {
    unsigned u;
    asm("cvt.rna.tf32.f32 %0, %1;" : "=r"(u) : "f"(f));
    return u;
}

// ---------------- init / CSR build ----------------
__global__ void init_kernel(const void* eidx, int n) {
    int i = blockIdx.x * blockDim.x + threadIdx.x;
    if (i < n) g_deg[i] = 0;
    if (i < NB_MAX) g_fsum[i] = 0;
    if (i == 0) {
        const long long* p = (const long long*)eidx;
        int ok = 1;
        #pragma unroll
        for (int k = 0; k < 32; k++) {
            long long v = p[k];
            if (v < 0 || v >= (long long)n) { ok = 0; break; }
        }
        g_is64 = ok;
    }
}

__global__ void hist_kernel(const void* eidx, int e) {
    int i = blockIdx.x * blockDim.x + threadIdx.x;
    if (i < e) {
        int d = edge_val(eidx, e + i, g_is64);
        atomicAdd(&g_deg[d], 1);
    }
}

// one-pass scan: local block scan + publish (incl+1), spin-sum predecessors.
// grid = nb (49) blocks, all co-resident on 148 SMs -> spin is deadlock-free.
__global__ void scan_onepass_kernel(int n) {
    __shared__ int wsum[32];
    __shared__ int s_pre;
    int t = threadIdx.x, lane = t & 31, wid = t >> 5, b = blockIdx.x;
    int gid = b * SCAN_B + t;
    int v = (gid < n) ? g_deg[gid] : 0;
    int x = v;
    #pragma unroll
    for (int o = 1; o < 32; o <<= 1) {
        int y = __shfl_up_sync(0xffffffffu, x, o);
        if (lane >= o) x += y;
    }
    if (lane == 31) wsum[wid] = x;
    __syncthreads();
    if (wid == 0) {
        int s = wsum[lane];
        #pragma unroll
        for (int o = 1; o < 32; o <<= 1) {
            int y = __shfl_up_sync(0xffffffffu, s, o);
            if (lane >= o) s += y;
        }
        wsum[lane] = s;
    }
    __syncthreads();
    int incl = x + (wid > 0 ? wsum[wid - 1] : 0);

    // publish this block's total (warp 31 holds it at t == SCAN_B-1)
    if (t == SCAN_B - 1) g_fsum[b] = incl + 1;          // single-word publish

    // warp 0: spin-sum all predecessor block totals
    if (wid == 0) {
        int p = 0;
        for (int i = lane; i < b; i += 32) {
            int fv;
            while ((fv = g_fsum[i]) == 0) { }
            p += fv - 1;
        }
        #pragma unroll
        for (int o = 16; o >= 1; o >>= 1)
            p += __shfl_xor_sync(0xffffffffu, p, o);
        if (lane == 0) s_pre = p;
    }
    __syncthreads();
    if (gid < n) g_offs[gid] = (incl - v) + s_pre;      // global exclusive
}

// scatter bumps g_offs[d] directly: afterwards g_offs[v] = segment end.
__global__ void scatter_kernel(const void* eidx, int e) {
    int i = blockIdx.x * blockDim.x + threadIdx.x;
    if (i < e) {
        int is64 = g_is64;
        int d = edge_val(eidx, e + i, is64);
        int s = edge_val(eidx, i, is64);
        int pos = atomicAdd(&g_offs[d], 1);
        g_csr[pos] = s;
    }
}

// ---------------- GEMM: H = X @ W^T via tf32 mma.sync -------------------
#define XP 68
#define SX_F (128 * XP)
#define SW_F (D * XP)
#define GEMM_SMEM ((SX_F + SW_F) * 4)

__global__ void __launch_bounds__(256) gemm_kernel(
        const float* __restrict__ X, const float* __restrict__ W,
        const float* __restrict__ a_src, const float* __restrict__ a_dst, int n) {
    extern __shared__ __align__(16) unsigned smu[];
    unsigned* sX = smu;            // [r][k] tf32 bits, pitch XP
    unsigned* sW = smu + SX_F;     // [c][k] tf32 bits, pitch XP

    int t = threadIdx.x;
    int base = blockIdx.x * 128;

    {
        const float4* Xv = (const float4*)X;
        #pragma unroll
        for (int idx = t; idx < 128 * 16; idx += 256) {
            int r = idx >> 4, q = idx & 15;
            int gr = base + r;
            float4 v = make_float4(0.f, 0.f, 0.f, 0.f);
            if (gr < n) v = Xv[gr * 16 + q];
            uint4 u;
            u.x = f2tf32(v.x); u.y = f2tf32(v.y);
            u.z = f2tf32(v.z); u.w = f2tf32(v.w);
            *reinterpret_cast<uint4*>(&sX[r * XP + q * 4]) = u;
        }
    }
    {
        const float4* Wv = (const float4*)W;
        #pragma unroll
        for (int idx = t; idx < 64 * 16; idx += 256) {
            int c = idx >> 4, q = idx & 15;
            float4 v = Wv[idx];
            uint4 u;
            u.x = f2tf32(v.x); u.y = f2tf32(v.y);
            u.z = f2tf32(v.z); u.w = f2tf32(v.w);
            *reinterpret_cast<uint4*>(&sW[c * XP + q * 4]) = u;
        }
    }
    __syncthreads();

    int lane = t & 31;
    int wr   = (t >> 5) << 4;
    int gid  = lane >> 2;
    int tig  = lane & 3;

    float c[8][4];
    #pragma unroll
    for (int nt = 0; nt < 8; nt++)
        #pragma unroll
        for (int j = 0; j < 4; j++) c[nt][j] = 0.f;

    const unsigned* arow0 = &sX[(wr + gid) * XP + tig];
    const unsigned* arow1 = arow0 + 8 * XP;
    const unsigned* brow  = &sW[gid * XP + tig];

    #pragma unroll
    for (int ks = 0; ks < 8; ks++) {
        int k0 = ks * 8;
        unsigned a0 = arow0[k0];
        unsigned a1 = arow1[k0];
        unsigned a2 = arow0[k0 + 4];
        unsigned a3 = arow1[k0 + 4];
        #pragma unroll
        for (int nt = 0; nt < 8; nt++) {
            unsigned b0 = brow[nt * 8 * XP + k0];
            unsigned b1 = brow[nt * 8 * XP + k0 + 4];
            asm volatile(
                "mma.sync.aligned.m16n8k8.row.col.f32.tf32.tf32.f32 "
                "{%0,%1,%2,%3}, {%4,%5,%6,%7}, {%8,%9}, {%0,%1,%2,%3};"
                : "+f"(c[nt][0]), "+f"(c[nt][1]), "+f"(c[nt][2]), "+f"(c[nt][3])
                : "r"(a0), "r"(a1), "r"(a2), "r"(a3), "r"(b0), "r"(b1));
        }
    }

    int gr0 = base + wr + gid;
    int gr1 = gr0 + 8;
    float asp0 = 0.f, adp0 = 0.f, asp1 = 0.f, adp1 = 0.f;
    #pragma unroll
    for (int nt = 0; nt < 8; nt++) {
        int col = nt * 8 + tig * 2;
        float sa0 = a_src[col], sa1 = a_src[col + 1];
        float da0 = a_dst[col], da1 = a_dst[col + 1];
        asp0 += c[nt][0] * sa0 + c[nt][1] * sa1;
        adp0 += c[nt][0] * da0 + c[nt][1] * da1;
        asp1 += c[nt][2] * sa0 + c[nt][3] * sa1;
        adp1 += c[nt][2] * da0 + c[nt][3] * da1;

        __half2 h01 = __floats2half2_rn(c[nt][0], c[nt][1]);
        __half2 h23 = __floats2half2_rn(c[nt][2], c[nt][3]);
        if (gr0 < n) *reinterpret_cast<__half2*>(&g_h[gr0 * D + col]) = h01;
        if (gr1 < n) *reinterpret_cast<__half2*>(&g_h[gr1 * D + col]) = h23;
    }
    #pragma unroll
    for (int o = 1; o <= 2; o <<= 1) {
        asp0 += __shfl_xor_sync(0xffffffffu, asp0, o);
        adp0 += __shfl_xor_sync(0xffffffffu, adp0, o);
        asp1 += __shfl_xor_sync(0xffffffffu, asp1, o);
        adp1 += __shfl_xor_sync(0xffffffffu, adp1, o);
    }
    if (tig == 0) {
        if (gr0 < n) { g_as[gr0] = asp0; g_ad[gr0] = adp0; }
        if (gr1 < n) { g_as[gr1] = asp1; g_ad[gr1] = adp1; }
    }
}

// ---------------- aggregation: 4 nodes/warp, 8 lanes/node, x4 batched -----
__global__ void agg_kernel(const float* __restrict__ b, int n, int last,
                           const float* __restrict__ Wout,
                           const float* __restrict__ bout,
                           float* __restrict__ out) {
    int wid_g = (blockIdx.x * blockDim.x + threadIdx.x) >> 5;
    int lane = threadIdx.x & 31;
    if (wid_g * 4 >= n) return;
    int sub = lane >> 3, sl = lane & 7;
    int v = wid_g * 4 + sub;
    bool valid = v < n;
    int vc = valid ? v : (n - 1);

    int end = __ldg(&g_offs[vc]);
    int dg  = __ldg(&g_deg[vc]);
    int beg = end - dg;
    int deg = valid ? dg : 0;
    float adv = g_ad[vc];
    int c0 = sl * 8;

    float acc[8];
    float denom;
    {
        float w0 = valid ? __expf(lrelu(g_as[vc] + adv, 0.2f)) : 0.f;
        denom = w0;
        uint4 pk = __ldg(reinterpret_cast<const uint4*>(&g_h[vc * D + c0]));
        const __half2* hp = reinterpret_cast<const __half2*>(&pk);
        #pragma unroll
        for (int q = 0; q < 4; q++) {
            float2 f = __half22float2(hp[q]);
            acc[q * 2]     = w0 * f.x;
            acc[q * 2 + 1] = w0 * f.y;
        }
    }

    int mx = deg;
    #pragma unroll
    for (int o = 16; o >= 1; o >>= 1)
        mx = max(mx, __shfl_xor_sync(0xffffffffu, mx, o));

    int i = 0;
    for (; i + 4 <= mx; i += 4) {
        bool b0 = i < deg, b1 = i + 1 < deg, b2 = i + 2 < deg, b3 = i + 3 < deg;
        int p = beg + i;
        int s0 = b0 ? __ldg(&g_csr[p])     : vc;
        int s1 = b1 ? __ldg(&g_csr[p + 1]) : vc;
        int s2 = b2 ? __ldg(&g_csr[p + 2]) : vc;
        int s3 = b3 ? __ldg(&g_csr[p + 3]) : vc;
        float as0 = __ldg(&g_as[s0]), as1 = __ldg(&g_as[s1]);
        float as2 = __ldg(&g_as[s2]), as3 = __ldg(&g_as[s3]);
        uint4 p0 = __ldg(reinterpret_cast<const uint4*>(&g_h[s0 * D + c0]));
        uint4 p1 = __ldg(reinterpret_cast<const uint4*>(&g_h[s1 * D + c0]));
        uint4 p2 = __ldg(reinterpret_cast<const uint4*>(&g_h[s2 * D + c0]));
        uint4 p3 = __ldg(reinterpret_cast<const uint4*>(&g_h[s3 * D + c0]));
        float e0 = b0 ? __expf(lrelu(as0 + adv, 0.2f)) : 0.f;
        float e1 = b1 ? __expf(lrelu(as1 + adv, 0.2f)) : 0.f;
        float e2 = b2 ? __expf(lrelu(as2 + adv, 0.2f)) : 0.f;
        float e3 = b3 ? __expf(lrelu(as3 + adv, 0.2f)) : 0.f;
        const __half2* h0 = reinterpret_cast<const __half2*>(&p0);
        const __half2* h1 = reinterpret_cast<const __half2*>(&p1);
        const __half2* h2 = reinterpret_cast<const __half2*>(&p2);
        const __half2* h3 = reinterpret_cast<const __half2*>(&p3);
        denom += (e0 + e1) + (e2 + e3);
        #pragma unroll
        for (int q = 0; q < 4; q++) {
            float2 f0 = __half22float2(h0[q]);
            float2 f1 = __half22float2(h1[q]);
            float2 f2 = __half22float2(h2[q]);
            float2 f3 = __half22float2(h3[q]);
            acc[q * 2]     += (e0 * f0.x + e1 * f1.x) + (e2 * f2.x + e3 * f3.x);
            acc[q * 2 + 1] += (e0 * f0.y + e1 * f1.y) + (e2 * f2.y + e3 * f3.y);
        }
    }
    for (; i < mx; i++) {
        bool bv = i < deg;
        int p = beg + i;
        int s0 = bv ? __ldg(&g_csr[p]) : vc;
        float e0 = bv ? __expf(lrelu(__ldg(&g_as[s0]) + adv, 0.2f)) : 0.f;
        uint4 pk = __ldg(reinterpret_cast<const uint4*>(&g_h[s0 * D + c0]));
        const __half2* hp = reinterpret_cast<const __half2*>(&pk);
        denom += e0;
        #pragma unroll
        for (int q = 0; q < 4; q++) {
            float2 f = __half22float2(hp[q]);
            acc[q * 2]     += e0 * f.x;
            acc[q * 2 + 1] += e0 * f.y;
        }
    }

    float inv = valid ? (1.0f / denom) : 0.f;
    float o8[8];
    #pragma unroll
    for (int q = 0; q < 8; q++)
        o8[q] = lrelu(acc[q] * inv + b[c0 + q], 0.01f);

    if (!last) {
        if (valid) {
            float4 va; va.x = o8[0]; va.y = o8[1]; va.z = o8[2]; va.w = o8[3];
            float4 vb; vb.x = o8[4]; vb.y = o8[5]; vb.z = o8[6]; vb.w = o8[7];
            *reinterpret_cast<float4*>(&g_a[v * D + c0])     = va;
            *reinterpret_cast<float4*>(&g_a[v * D + c0 + 4]) = vb;
        }
    } else {
        float s = 0.f;
        #pragma unroll
        for (int q = 0; q < 8; q++) s += o8[q] * Wout[c0 + q];
        #pragma unroll
        for (int o = 4; o >= 1; o >>= 1)
            s += __shfl_xor_sync(0xffffffffu, s, o);
        if (sl == 0 && valid) out[v] = s + bout[0];
    }
}

// ---------------- launch: fork-join overlap of CSR chain with gemm0 -------
extern "C" void kernel_launch(void* const* d_in, const int* in_sizes, int n_in,
                              void* d_out, int out_size) {
    const float* x = (const float*)d_in[0];
    const float* W[3]    = {(const float*)d_in[1], (const float*)d_in[5], (const float*)d_in[9]};
    const float* asrc[3] = {(const float*)d_in[2], (const float*)d_in[6], (const float*)d_in[10]};
    const float* adst[3] = {(const float*)d_in[3], (const float*)d_in[7], (const float*)d_in[11]};
    const float* bias[3] = {(const float*)d_in[4], (const float*)d_in[8], (const float*)d_in[12]};
    const float* Wout = (const float*)d_in[13];
    const float* bout = (const float*)d_in[14];
    const void*  eidx = d_in[15];

    int n = in_sizes[0] / D;
    int e = in_sizes[15] / 2;

    void* a_ptr = nullptr;
    cudaGetSymbolAddress(&a_ptr, g_a);
    const float* abuf = (const float*)a_ptr;

    cudaFuncSetAttribute(gemm_kernel,
                         cudaFuncAttributeMaxDynamicSharedMemorySize, GEMM_SMEM);

    cudaStream_t s2 = nullptr;
    cudaEvent_t evFork = nullptr, evJoin = nullptr;
    {
        cudaStreamCaptureMode mode = cudaStreamCaptureModeRelaxed;
        cudaThreadExchangeStreamCaptureMode(&mode);
        cudaStreamCreateWithFlags(&s2, cudaStreamNonBlocking);
        cudaEventCreateWithFlags(&evFork, cudaEventDisableTiming);
        cudaEventCreateWithFlags(&evJoin, cudaEventDisableTiming);
        cudaThreadExchangeStreamCaptureMode(&mode);
    }

    int nb = (n + SCAN_B - 1) / SCAN_B;
    int eb = (e + 255) / 256;
    int zb = (n + 255) / 256;
    int gemm_b = (n + 127) / 128;
    int agg_b  = ((n + 3) / 4 * 32 + 255) / 256;

    // fork: CSR chain on s2, gemm0 on default stream
    cudaEventRecord(evFork, 0);
    cudaStreamWaitEvent(s2, evFork, 0);

    init_kernel<<<zb, 256, 0, s2>>>(eidx, n);
    hist_kernel<<<eb, 256, 0, s2>>>(eidx, e);
    scan_onepass_kernel<<<nb, SCAN_B, 0, s2>>>(n);
    scatter_kernel<<<eb, 256, 0, s2>>>(eidx, e);
    cudaEventRecord(evJoin, s2);

    gemm_kernel<<<gemm_b, 256, GEMM_SMEM>>>(x, W[0], asrc[0], adst[0], n);

    // join before agg0 (needs CSR + gemm0)
    cudaStreamWaitEvent(0, evJoin, 0);
    agg_kernel<<<agg_b, 256>>>(bias[0], n, 0, Wout, bout, (float*)d_out);

    for (int l = 1; l < 3; l++) {
        gemm_kernel<<<gemm_b, 256, GEMM_SMEM>>>(abuf, W[l], asrc[l], adst[l], n);
        agg_kernel<<<agg_b, 256>>>(bias[l], n, (l == 2) ? 1 : 0,
                                   Wout, bout, (float*)d_out);
    }
}